// round 4
// baseline (speedup 1.0000x reference)
#include <cuda_runtime.h>
#include <cuda_bf16.h>
#include <cstdint>

// GTN collapses (softmax over singleton axis == 1 -> gtconv == 2*A):
//   H   = 4*(A@A) + I
//   inv = 2 / rowsum(H)   (guarded)
//   out = diag(inv) @ (H @ A)
// tcgen05 unavailable (harness PTX targets plain sm_103); GEMMs run on
// mma.sync bf16 HMMA with cp.async pipelines + register-fragment double buffering.

#define NMAT 2048
static constexpr int BM = 128;
static constexpr int BN = 128;
static constexpr int BK = 32;
static constexpr int STAGES = 4;
static constexpr int KT = NMAT / BK;            // 64
static constexpr int STAGE_BYTES = BM * 64;     // 8KB
static constexpr int SMEM_B_OFF = STAGES * STAGE_BYTES;
static constexpr int SMEM_DYN = 2 * STAGES * STAGE_BYTES;    // 64KB

__device__ __nv_bfloat16 g_Abf[(size_t)NMAT * NMAT];
__device__ __nv_bfloat16 g_ATbf[(size_t)NMAT * NMAT];
__device__ __nv_bfloat16 g_Hbf[(size_t)NMAT * NMAT];
__device__ float g_rowpart[2][NMAT / BN][NMAT];
__device__ float g_inv[NMAT];

__device__ __forceinline__ uint32_t smem_u32(const void* p) {
    uint32_t a;
    asm("{ .reg .u64 t; cvta.to.shared.u64 t, %1; cvt.u32.u64 %0, t; }" : "=r"(a) : "l"(p));
    return a;
}
#define CP_ASYNC16(dst, src) asm volatile("cp.async.cg.shared.global [%0], [%1], 16;" :: "r"(dst), "l"(src) : "memory")
#define CP_COMMIT()          asm volatile("cp.async.commit_group;" ::: "memory")
#define CP_WAIT2()           asm volatile("cp.async.wait_group 2;" ::: "memory")
#define LDSM_X4(r0, r1, r2, r3, a) \
    asm volatile("ldmatrix.sync.aligned.m8n8.x4.shared.b16 {%0,%1,%2,%3}, [%4];" \
                 : "=r"(r0), "=r"(r1), "=r"(r2), "=r"(r3) : "r"(a))
#define MMA_BF16(c, a, b) \
    asm volatile("mma.sync.aligned.m16n8k16.row.col.f32.bf16.bf16.f32 " \
                 "{%0,%1,%2,%3}, {%4,%5,%6,%7}, {%8,%9}, {%0,%1,%2,%3};" \
                 : "+f"((c)[0]), "+f"((c)[1]), "+f"((c)[2]), "+f"((c)[3]) \
                 : "r"((a)[0]), "r"((a)[1]), "r"((a)[2]), "r"((a)[3]), "r"((b)[0]), "r"((b)[1]))

__device__ __forceinline__ uint32_t swz(int row, int colb) {
    return (uint32_t)(row * 64 + (colb ^ (((row >> 1) & 3) << 4)));
}

// ---------------- A -> bf16 and A^T -> bf16 ----------------
__global__ void convert_kernel(const float* __restrict__ A)
{
    __shared__ float t[32][33];
    const int tx = threadIdx.x, ty = threadIdx.y;
    const int x = blockIdx.x * 32 + tx;
    const int y0 = blockIdx.y * 32;
#pragma unroll
    for (int j = 0; j < 32; j += 8) {
        const int row = y0 + j + ty;
        const float v = A[(size_t)row * NMAT + x];
        t[j + ty][tx] = v;
        g_Abf[(size_t)row * NMAT + x] = __float2bfloat16(v);
    }
    __syncthreads();
    const int nx = y0 + tx;
#pragma unroll
    for (int j = 0; j < 32; j += 8) {
        const int orow = blockIdx.x * 32 + j + ty;
        g_ATbf[(size_t)orow * NMAT + nx] = __float2bfloat16(t[tx][j + ty]);
    }
}

__global__ void invdeg_kernel()
{
    const int r = blockIdx.x * 256 + threadIdx.x;
    float d = 0.f;
#pragma unroll
    for (int h = 0; h < 2; h++)
#pragma unroll
        for (int t = 0; t < NMAT / BN; t++) d += g_rowpart[h][t][r];
    if (d <= 1e-10f) d = 1.f;
    g_inv[r] = 2.f / d;
}

// ---------------- HMMA GEMM with fragment double buffering ----------------
template <int MODE>
__launch_bounds__(256, 2)
__global__ void gemm_mma(float* __restrict__ Cout)
{
    extern __shared__ char dyn_raw[];
    const uint32_t sb = smem_u32(dyn_raw);

    const int tid = threadIdx.x;
    const int lane = tid & 31;
    const int wid = tid >> 5;
    const int warp_m = wid & 3;
    const int warp_n = wid >> 2;
    const int row0 = blockIdx.y * BM;
    const int col0 = blockIdx.x * BN;

    const __nv_bfloat16* __restrict__ Lop = (MODE == 0) ? g_Abf : g_Hbf;
    const __nv_bfloat16* __restrict__ Rop = g_ATbf;

    // Lane-constant fragment offsets within a stage, per k16 step
    uint32_t aoff[2][2], boff[2][4];
#pragma unroll
    for (int st = 0; st < 2; st++) {
#pragma unroll
        for (int mt = 0; mt < 2; mt++)
            aoff[st][mt] = swz(warp_m * 32 + mt * 16 + (lane & 15),
                               st * 32 + ((lane >> 4) << 4));
#pragma unroll
        for (int np = 0; np < 4; np++)
            boff[st][np] = swz(warp_n * 64 + np * 16 + (lane & 7) + ((lane >> 4) << 3),
                               st * 32 + (((lane >> 3) & 1) << 4));
    }

    auto fill = [&](int kt, int s) {
        const uint32_t ab = sb + s * STAGE_BYTES;
        const uint32_t bb = sb + SMEM_B_OFF + s * STAGE_BYTES;
#pragma unroll
        for (int i = 0; i < 2; i++) {
            const int ch = i * 256 + tid;
            const int row = ch >> 2, c16 = ch & 3;
            CP_ASYNC16(ab + swz(row, c16 * 16),
                       Lop + (size_t)(row0 + row) * NMAT + kt * BK + c16 * 8);
            CP_ASYNC16(bb + swz(row, c16 * 16),
                       Rop + (size_t)(col0 + row) * NMAT + kt * BK + c16 * 8);
        }
    };

    auto ldsm_frag = [&](uint32_t a[2][4], uint32_t b[4][4], int s, int st) {
        const uint32_t ab = sb + s * STAGE_BYTES;
        const uint32_t bb = sb + SMEM_B_OFF + s * STAGE_BYTES;
#pragma unroll
        for (int mt = 0; mt < 2; mt++)
            LDSM_X4(a[mt][0], a[mt][1], a[mt][2], a[mt][3], ab + aoff[st][mt]);
#pragma unroll
        for (int np = 0; np < 4; np++)
            LDSM_X4(b[np][0], b[np][1], b[np][2], b[np][3], bb + boff[st][np]);
    };

    float acc[2][8][4];
#pragma unroll
    for (int mt = 0; mt < 2; mt++)
#pragma unroll
        for (int nt = 0; nt < 8; nt++)
#pragma unroll
            for (int j = 0; j < 4; j++) acc[mt][nt][j] = 0.f;

    auto mma_burst = [&](uint32_t a[2][4], uint32_t b[4][4]) {
#pragma unroll
        for (int mt = 0; mt < 2; mt++)
#pragma unroll
            for (int nt = 0; nt < 8; nt++) {
                uint32_t bf[2] = {b[nt >> 1][(nt & 1) * 2], b[nt >> 1][(nt & 1) * 2 + 1]};
                MMA_BF16(acc[mt][nt], a[mt], bf);
            }
    };

    // Prologue
    fill(0, 0); CP_COMMIT();
    fill(1, 1); CP_COMMIT();
    fill(2, 2); CP_COMMIT();
    CP_WAIT2();
    __syncthreads();

    uint32_t a0[2][4], b0[4][4], a1[2][4], b1[4][4];
    ldsm_frag(a0, b0, 0, 0);     // (kt=0, step 0)

    for (int kt = 0; kt < KT; kt++) {
        const int s = kt & (STAGES - 1);

        ldsm_frag(a1, b1, s, 1);             // step-1 frags (last read of stage s's step1)
        const int f = kt + 3;
        if (f < KT) fill(f, f & (STAGES - 1));   // overwrites stage (kt-1)&3: barrier-protected
        CP_COMMIT();

        mma_burst(a0, b0);                   // step 0 — hides LDSM + LDG latencies

        if (kt + 1 < KT) {
            CP_WAIT2();                      // tile kt+1 resident
            __syncthreads();
            ldsm_frag(a0, b0, (kt + 1) & (STAGES - 1), 0);   // next tile's step-0 frags
        }

        mma_burst(a1, b1);                   // step 1 — hides next-tile LDSM + barrier
    }

    // ---------------- epilogue ----------------
#pragma unroll
    for (int mt = 0; mt < 2; mt++) {
        const int rA = row0 + warp_m * 32 + mt * 16 + (lane >> 2);
        const float s0 = (MODE == 0) ? 4.0f : g_inv[rA];
        const float s1 = (MODE == 0) ? 4.0f : g_inv[rA + 8];
        float rs0 = 0.f, rs1 = 0.f;
#pragma unroll
        for (int nt = 0; nt < 8; nt++) {
            const int c = col0 + warp_n * 64 + nt * 8 + (lane & 3) * 2;
            float v0 = s0 * acc[mt][nt][0];
            float v1 = s0 * acc[mt][nt][1];
            float v2 = s1 * acc[mt][nt][2];
            float v3 = s1 * acc[mt][nt][3];
            if (MODE == 0) {
                if (rA == c)         v0 += 1.0f;
                if (rA == c + 1)     v1 += 1.0f;
                if (rA + 8 == c)     v2 += 1.0f;
                if (rA + 8 == c + 1) v3 += 1.0f;
                rs0 += v0 + v1;
                rs1 += v2 + v3;
                *reinterpret_cast<__nv_bfloat162*>(g_Hbf + (size_t)rA * NMAT + c) =
                    __floats2bfloat162_rn(v0, v1);
                *reinterpret_cast<__nv_bfloat162*>(g_Hbf + (size_t)(rA + 8) * NMAT + c) =
                    __floats2bfloat162_rn(v2, v3);
            } else {
                *reinterpret_cast<float2*>(Cout + (size_t)rA * NMAT + c) = make_float2(v0, v1);
                *reinterpret_cast<float2*>(Cout + (size_t)(rA + 8) * NMAT + c) = make_float2(v2, v3);
            }
        }
        if (MODE == 0) {
            rs0 += __shfl_xor_sync(0xFFFFFFFF, rs0, 1);
            rs0 += __shfl_xor_sync(0xFFFFFFFF, rs0, 2);
            rs1 += __shfl_xor_sync(0xFFFFFFFF, rs1, 1);
            rs1 += __shfl_xor_sync(0xFFFFFFFF, rs1, 2);
            if ((lane & 3) == 0) {
                g_rowpart[warp_n][blockIdx.x][rA] = rs0;
                g_rowpart[warp_n][blockIdx.x][rA + 8] = rs1;
            }
        }
    }
}

extern "C" void kernel_launch(void* const* d_in, const int* in_sizes, int n_in,
                              void* d_out, int out_size)
{
    const float* A = (const float*)d_in[0];   // weights unused: softmax over singleton == 1
    float* out = (float*)d_out;

    cudaFuncSetAttribute(gemm_mma<0>, cudaFuncAttributeMaxDynamicSharedMemorySize, SMEM_DYN);
    cudaFuncSetAttribute(gemm_mma<1>, cudaFuncAttributeMaxDynamicSharedMemorySize, SMEM_DYN);

    convert_kernel<<<dim3(NMAT / 32, NMAT / 32), dim3(32, 8)>>>(A);
    gemm_mma<0><<<dim3(NMAT / BN, NMAT / BM), 256, SMEM_DYN>>>(out);   // H = 4*A@A + I
    invdeg_kernel<<<NMAT / 256, 256>>>();
    gemm_mma<1><<<dim3(NMAT / BN, NMAT / BM), 256, SMEM_DYN>>>(out);   // out = diag(2/deg)@(H@A)
}